// round 5
// baseline (speedup 1.0000x reference)
#include <cuda_runtime.h>

// Problem constants (fixed shapes: B=8, K=4, N=131072)
#define TOT    4194304          // B*K*N
#define NDIM   131072           // N
#define CHUNK  2048             // elements per block
#define NBLK   2048             // TOT / CHUNK
#define NEG_PAD  (-1000.0f)
#define NEG_IDLE (-100000000.0f)

#define ST_AGG 1ULL
#define ST_INC 2ULL

// Static device state (zero-initialized at module load; the last block of
// every launch resets it to zero, so each run starts identically).
__device__ unsigned long long g_desc[NBLK];   // [63:62]=status [61:31]=S [30:0]=A
__device__ unsigned int       g_done;

// bytes of w are 0/1 -> 4-bit mask (bit j = byte j)
__device__ __forceinline__ unsigned int nib01(unsigned int w) {
    return (w * 0x01020408u) >> 24;
}
// could this word belong to a word-per-element (int32/float32 0/1) mask?
__device__ __forceinline__ bool wordlike(unsigned int w) {
    return (w == 0u) | (w == 1u) | (w == 0x3f800000u);
}

__device__ __forceinline__ unsigned long long desc_pack(unsigned long long st,
                                                        unsigned int s, unsigned int a) {
    return (st << 62) | ((unsigned long long)s << 31) | (unsigned long long)a;
}

// ---------------------------------------------------------------------------
// Single fused kernel: detect + count + decoupled-lookback scan + gather/emit.
// 2048 blocks x 256 threads, 8 elements/thread.
// Output layout (flattened tuple): [rgb_out 3*TOT][ls_out TOT][la_out TOT]
// ---------------------------------------------------------------------------
__global__ void __launch_bounds__(256)
fused_kernel(const void* __restrict__ msRaw,
             const void* __restrict__ maRaw,
             const float* __restrict__ rgb,
             const float* __restrict__ lsf,
             const float* __restrict__ lar,
             const float* __restrict__ idle_states,
             float* __restrict__ out) {
    const int t    = threadIdx.x;
    const int b    = blockIdx.x;
    const int base = b * CHUNK;
    const int i0   = base + t * 8;
    const int lane = t & 31, wid = t >> 5;

    __shared__ unsigned int wTot[8], wPre[8];
    __shared__ unsigned int shTot, shExcS, shExcA;
    __shared__ int shLast;

    // --- 1. load masks assuming byte-per-element; vote to detect dtype ---
    uint2 sB = ((const uint2*)msRaw)[i0 >> 3];
    uint2 aB = ((const uint2*)maRaw)[i0 >> 3];
    int bad = (!wordlike(sB.x)) | (!wordlike(sB.y)) |
              (!wordlike(aB.x)) | (!wordlike(aB.y));
    int byteKind = __syncthreads_or(bad);   // any non-wordlike word => byte masks

    unsigned int mS, mA;
    if (byteKind) {
        mS = nib01(sB.x) | (nib01(sB.y) << 4);
        mA = nib01(aB.x) | (nib01(aB.y) << 4);
    } else {
        // word-per-element (int32 0/1 or float32 0.0/1.0): nonzero => true
        const uint4* ps = (const uint4*)msRaw + (i0 >> 2);
        const uint4* pa = (const uint4*)maRaw + (i0 >> 2);
        uint4 s0 = ps[0], s1 = ps[1];
        uint4 a0 = pa[0], a1 = pa[1];
        mS =  (s0.x ? 1u : 0u)  | (s0.y ? 2u : 0u)  | (s0.z ? 4u : 0u)  | (s0.w ? 8u : 0u)
           |  (s1.x ? 16u : 0u) | (s1.y ? 32u : 0u) | (s1.z ? 64u : 0u) | (s1.w ? 128u : 0u);
        mA =  (a0.x ? 1u : 0u)  | (a0.y ? 2u : 0u)  | (a0.z ? 4u : 0u)  | (a0.w ? 8u : 0u)
           |  (a1.x ? 16u : 0u) | (a1.y ? 32u : 0u) | (a1.z ? 64u : 0u) | (a1.w ? 128u : 0u);
    }

    // --- 2. packed 16+16 block-wide scan (block totals <= 2048 each) ---
    unsigned int packed = __popc(mS) | (__popc(mA) << 16);
    unsigned int inc = packed;
#pragma unroll
    for (int d = 1; d < 32; d <<= 1) {
        unsigned int v = __shfl_up_sync(0xffffffffu, inc, d);
        if (lane >= d) inc += v;
    }
    if (lane == 31) wTot[wid] = inc;
    __syncthreads();

    // --- 3. warp 0: publish aggregate, lookback, publish inclusive ---
    if (wid == 0) {
        if (lane == 0) {
            unsigned int run = 0;
#pragma unroll
            for (int w = 0; w < 8; ++w) { wPre[w] = run; run += wTot[w]; }
            shTot = run;
            if (b > 0) {
                unsigned int totS = run & 0xFFFFu, totA = run >> 16;
                *(volatile unsigned long long*)(g_desc + b) = desc_pack(ST_AGG, totS, totA);
            }
        }
        __syncwarp();
        unsigned int accS = 0, accA = 0;
        if (b > 0) {
            int look = b - 1 - lane;
            while (true) {
                unsigned long long d;
                if (look >= 0) {
                    do {
                        d = *(volatile unsigned long long*)(g_desc + look);
                    } while ((unsigned int)(d >> 62) == 0u);
                } else {
                    d = desc_pack(ST_INC, 0u, 0u);   // virtual inclusive-zero
                }
                unsigned int st = (unsigned int)(d >> 62);
                unsigned int ball = __ballot_sync(0xffffffffu, st == (unsigned int)ST_INC);
                unsigned int vS = (unsigned int)((d >> 31) & 0x7FFFFFFFu);
                unsigned int vA = (unsigned int)(d & 0x7FFFFFFFu);
                if (ball) {
                    int L = __ffs(ball) - 1;        // closest inclusive prefix
                    if (lane > L) { vS = 0u; vA = 0u; }
#pragma unroll
                    for (int o = 16; o > 0; o >>= 1) {
                        vS += __shfl_down_sync(0xffffffffu, vS, o);
                        vA += __shfl_down_sync(0xffffffffu, vA, o);
                    }
                    if (lane == 0) { accS += vS; accA += vA; }
                    break;
                } else {                            // 32 aggregates: sum, step back
#pragma unroll
                    for (int o = 16; o > 0; o >>= 1) {
                        vS += __shfl_down_sync(0xffffffffu, vS, o);
                        vA += __shfl_down_sync(0xffffffffu, vA, o);
                    }
                    if (lane == 0) { accS += vS; accA += vA; }
                    look -= 32;
                }
            }
        }
        if (lane == 0) {
            shExcS = accS;
            shExcA = accA;
            unsigned int totS = shTot & 0xFFFFu, totA = shTot >> 16;
            *(volatile unsigned long long*)(g_desc + b) =
                desc_pack(ST_INC, accS + totS, accA + totA);
        }
    }
    __syncthreads();

    const unsigned int exc   = wPre[wid] + inc - packed;
    unsigned int posS0 = shExcS + (exc & 0xFFFFu);
    unsigned int posA0 = shExcA + (exc >> 16);

    // whole block lies in one (b,k) row (CHUNK divides NDIM, base aligned)
    const int bk = base / NDIM;
    const float idle  = idle_states[bk];
    const float alive = 1.0f - idle;
    const float idn   = idle * NEG_IDLE;

    float* rgbOut = out;
    float* lsOut  = out + (size_t)3 * TOT;
    float* laOut  = out + (size_t)4 * TOT;

#pragma unroll
    for (int g = 0; g < 2; ++g) {
        float rv[12], lv[4], av[4];
#pragma unroll
        for (int j = 0; j < 4; ++j) {
            const int e = g * 4 + j;
            const unsigned int below = (1u << e) - 1u;
            if ((mS >> e) & 1u) {
                const unsigned int p = posS0 + __popc(mS & below);
                const float* rp = rgb + (size_t)p * 3;
                rv[3*j+0] = __ldg(rp + 0) * alive;
                rv[3*j+1] = __ldg(rp + 1) * alive;
                rv[3*j+2] = __ldg(rp + 2) * alive;
                lv[j] = __ldg(lsf + p) * alive + idn;
            } else {
                rv[3*j+0] = 0.0f; rv[3*j+1] = 0.0f; rv[3*j+2] = 0.0f;
                lv[j] = NEG_PAD;
            }
            if ((mA >> e) & 1u) {
                const unsigned int p = posA0 + __popc(mA & below);
                av[j] = __ldg(lar + p) * alive + idn;
            } else {
                av[j] = NEG_PAD;
            }
        }
        const int i = i0 + g * 4;                          // i % 4 == 0
        float4* rdst = (float4*)(rgbOut + (size_t)i * 3);  // 48B stride, 16B aligned
        rdst[0] = make_float4(rv[0], rv[1], rv[2],  rv[3]);
        rdst[1] = make_float4(rv[4], rv[5], rv[6],  rv[7]);
        rdst[2] = make_float4(rv[8], rv[9], rv[10], rv[11]);
        *(float4*)(lsOut + i) = make_float4(lv[0], lv[1], lv[2], lv[3]);
        *(float4*)(laOut + i) = make_float4(av[0], av[1], av[2], av[3]);
    }

    // --- 4. last block to finish resets the scan state for the next replay ---
    __syncthreads();
    if (t == 0) {
        __threadfence();                                   // order desc publish < counter
        unsigned int old = atomicAdd(&g_done, 1u);
        shLast = (old == (unsigned int)(NBLK - 1)) ? 1 : 0;
    }
    __syncthreads();
    if (shLast) {
        __threadfence();                                   // acquire: counter < clears
        for (int i = t; i < NBLK; i += 256)
            g_desc[i] = 0ULL;
        if (t == 0) g_done = 0u;
    }
}

// ---------------------------------------------------------------------------
// Inputs (metadata order): rgb, logits_surface, logits_air, idle_states,
//                          mask_eval_surface, mask_eval_air
// ---------------------------------------------------------------------------
extern "C" void kernel_launch(void* const* d_in, const int* in_sizes, int n_in,
                              void* d_out, int out_size) {
    (void)in_sizes; (void)n_in; (void)out_size;
    const float* rgb  = (const float*)d_in[0];
    const float* lsf  = (const float*)d_in[1];
    const float* lar  = (const float*)d_in[2];
    const float* idle = (const float*)d_in[3];
    const void*  ms   = d_in[4];
    const void*  ma   = d_in[5];

    fused_kernel<<<NBLK, 256>>>(ms, ma, rgb, lsf, lar, idle, (float*)d_out);
}

// round 8
// speedup vs baseline: 1.6179x; 1.6179x over previous
#include <cuda_runtime.h>

// Problem constants (fixed shapes: B=8, K=4, N=131072)
#define TOT    4194304          // B*K*N
#define NDIM   131072           // N
#define CHUNK  2048             // elements per block
#define NBLK   2048             // TOT / CHUNK
#define NEG_PAD  (-1000.0f)
#define NEG_IDLE (-100000000.0f)

// Per-chunk packed counts: S in low 16 bits, A in high 16 bits (each <= 2048).
// Rewritten by count_kernel every launch -> no cross-replay state.
__device__ unsigned int g_cnt[NBLK];

// bytes of w are 0/1 -> 4-bit mask (bit j = byte j)
__device__ __forceinline__ unsigned int nib01(unsigned int w) {
    return (w * 0x01020408u) >> 24;
}
// could this word belong to a word-per-element (int32/float32 0/1) mask?
__device__ __forceinline__ bool wordlike(unsigned int w) {
    return (w == 0u) | (w == 1u) | (w == 0x3f800000u);
}

// Load 8-element bitmasks for both mask arrays with per-block dtype vote.
// Byte masks (bool) contain some word != {0,1,1.0f} in a 2KB region with
// probability 1 - 0.343^1024 (i.e. certainty); word masks never do.
__device__ __forceinline__ void load_masks8(const void* __restrict__ msRaw,
                                            const void* __restrict__ maRaw,
                                            int i0,
                                            unsigned int& mS, unsigned int& mA) {
    uint2 sB = ((const uint2*)msRaw)[i0 >> 3];
    uint2 aB = ((const uint2*)maRaw)[i0 >> 3];
    int bad = (!wordlike(sB.x)) | (!wordlike(sB.y)) |
              (!wordlike(aB.x)) | (!wordlike(aB.y));
    int byteKind = __syncthreads_or(bad);
    if (byteKind) {
        mS = nib01(sB.x) | (nib01(sB.y) << 4);
        mA = nib01(aB.x) | (nib01(aB.y) << 4);
    } else {
        const uint4* ps = (const uint4*)msRaw + (i0 >> 2);
        const uint4* pa = (const uint4*)maRaw + (i0 >> 2);
        uint4 s0 = ps[0], s1 = ps[1];
        uint4 a0 = pa[0], a1 = pa[1];
        mS =  (s0.x ? 1u : 0u)  | (s0.y ? 2u : 0u)  | (s0.z ? 4u : 0u)  | (s0.w ? 8u : 0u)
           |  (s1.x ? 16u : 0u) | (s1.y ? 32u : 0u) | (s1.z ? 64u : 0u) | (s1.w ? 128u : 0u);
        mA =  (a0.x ? 1u : 0u)  | (a0.y ? 2u : 0u)  | (a0.z ? 4u : 0u)  | (a0.w ? 8u : 0u)
           |  (a1.x ? 16u : 0u) | (a1.y ? 32u : 0u) | (a1.z ? 64u : 0u) | (a1.w ? 128u : 0u);
    }
}

// ---------------------------------------------------------------------------
// Kernel 1: per-chunk counts (detect folded in). 2048 x 256, 8 elem/thread.
// ---------------------------------------------------------------------------
__global__ void __launch_bounds__(256)
count_kernel(const void* __restrict__ msRaw, const void* __restrict__ maRaw) {
    const int t  = threadIdx.x;
    const int i0 = blockIdx.x * CHUNK + t * 8;

    unsigned int mS, mA;
    load_masks8(msRaw, maRaw, i0, mS, mA);

    unsigned int p = __popc(mS) | (__popc(mA) << 16);   // block totals fit 16b each
#pragma unroll
    for (int d = 16; d > 0; d >>= 1)
        p += __shfl_down_sync(0xffffffffu, p, d);

    __shared__ unsigned int sw[8];
    const int lane = t & 31, wid = t >> 5;
    if (lane == 0) sw[wid] = p;
    __syncthreads();
    if (t == 0) {
        unsigned int tot = 0;
#pragma unroll
        for (int w = 0; w < 8; ++w) tot += sw[w];
        g_cnt[blockIdx.x] = tot;
    }
}

// ---------------------------------------------------------------------------
// Kernel 2: redundant per-block prefix over g_cnt (L2-resident), intra-block
// scan, gather + emit. rgb output staged through shared memory so all global
// stores are fully coalesced float4; streaming stores (__stcs) for output.
// Output layout (flattened tuple): [rgb_out 3*TOT][ls_out TOT][la_out TOT]
// ---------------------------------------------------------------------------
__global__ void __launch_bounds__(256)
output_kernel(const void* __restrict__ msRaw,
              const void* __restrict__ maRaw,
              const float* __restrict__ rgb,
              const float* __restrict__ lsf,
              const float* __restrict__ lar,
              const float* __restrict__ idle_states,
              float* __restrict__ out) {
    const int t    = threadIdx.x;
    const int b    = blockIdx.x;
    const int base = b * CHUNK;
    const int i0   = base + t * 8;
    const int lane = t & 31, wid = t >> 5;

    __shared__ float         sRGB[CHUNK * 3];          // 24 KB staging
    __shared__ unsigned int  wTot[8], wPre[8];
    __shared__ unsigned long long wAcc[8];
    __shared__ unsigned int  shPreS, shPreA;

    // --- masks (with per-block dtype vote) ---
    unsigned int mS, mA;
    load_masks8(msRaw, maRaw, i0, mS, mA);

    // --- global exclusive prefix: reduce g_cnt[idx] over idx < b ---
    unsigned int accS = 0, accA = 0;
#pragma unroll
    for (int w = 0; w < 8; ++w) {
        int idx = t + (w << 8);
        if (idx < b) {
            unsigned int c = g_cnt[idx];
            accS += c & 0xFFFFu;
            accA += c >> 16;
        }
    }
    unsigned long long acc = ((unsigned long long)accA << 32) | accS;
#pragma unroll
    for (int o = 16; o > 0; o >>= 1)
        acc += __shfl_down_sync(0xffffffffu, acc, o);
    if (lane == 0) wAcc[wid] = acc;

    // --- intra-block packed 16+16 scan ---
    unsigned int packed = __popc(mS) | (__popc(mA) << 16);
    unsigned int inc = packed;
#pragma unroll
    for (int d = 1; d < 32; d <<= 1) {
        unsigned int v = __shfl_up_sync(0xffffffffu, inc, d);
        if (lane >= d) inc += v;
    }
    if (lane == 31) wTot[wid] = inc;
    __syncthreads();
    if (t == 0) {
        unsigned long long g = 0;
        unsigned int run = 0;
#pragma unroll
        for (int w = 0; w < 8; ++w) {
            g += wAcc[w];
            wPre[w] = run; run += wTot[w];
        }
        shPreS = (unsigned int)(g & 0xffffffffu);
        shPreA = (unsigned int)(g >> 32);
    }
    __syncthreads();

    const unsigned int exc   = wPre[wid] + inc - packed;
    const unsigned int posS0 = shPreS + (exc & 0xFFFFu);
    const unsigned int posA0 = shPreA + (exc >> 16);

    // whole block lies in one (b,k) row (CHUNK divides NDIM, base aligned)
    const int bk = base / NDIM;
    const float idle  = idle_states[bk];
    const float alive = 1.0f - idle;
    const float idn   = idle * NEG_IDLE;

    float* lsOut  = out + (size_t)3 * TOT;
    float* laOut  = out + (size_t)4 * TOT;

    float4* sMine = (float4*)(sRGB + t * 24);   // 24 floats = 6 float4 per thread

#pragma unroll
    for (int g = 0; g < 2; ++g) {
        float rv[12], lv[4], av[4];
#pragma unroll
        for (int j = 0; j < 4; ++j) {
            const int e = g * 4 + j;
            const unsigned int below = (1u << e) - 1u;
            if ((mS >> e) & 1u) {
                const unsigned int p = posS0 + __popc(mS & below);
                const float* rp = rgb + (size_t)p * 3;
                rv[3*j+0] = __ldg(rp + 0) * alive;
                rv[3*j+1] = __ldg(rp + 1) * alive;
                rv[3*j+2] = __ldg(rp + 2) * alive;
                lv[j] = __ldg(lsf + p) * alive + idn;
            } else {
                rv[3*j+0] = 0.0f; rv[3*j+1] = 0.0f; rv[3*j+2] = 0.0f;
                lv[j] = NEG_PAD;
            }
            if ((mA >> e) & 1u) {
                const unsigned int p = posA0 + __popc(mA & below);
                av[j] = __ldg(lar + p) * alive + idn;
            } else {
                av[j] = NEG_PAD;
            }
        }
        // rgb -> shared staging (global write happens coalesced below)
        sMine[g*3 + 0] = make_float4(rv[0], rv[1], rv[2],  rv[3]);
        sMine[g*3 + 1] = make_float4(rv[4], rv[5], rv[6],  rv[7]);
        sMine[g*3 + 2] = make_float4(rv[8], rv[9], rv[10], rv[11]);
        // logits: already fully coalesced float4, streaming stores
        const int i = i0 + g * 4;
        __stcs((float4*)(lsOut + i), make_float4(lv[0], lv[1], lv[2], lv[3]));
        __stcs((float4*)(laOut + i), make_float4(av[0], av[1], av[2], av[3]));
    }

    // --- coalesced rgb writeback: 1536 float4 per block, 6 per thread ---
    __syncthreads();
    const float4* s4  = (const float4*)sRGB;
    float4*       dst = (float4*)(out + (size_t)base * 3);
#pragma unroll
    for (int k = 0; k < 6; ++k)
        __stcs(dst + t + (k << 8), s4[t + (k << 8)]);
}

// ---------------------------------------------------------------------------
// Inputs (metadata order): rgb, logits_surface, logits_air, idle_states,
//                          mask_eval_surface, mask_eval_air
// ---------------------------------------------------------------------------
extern "C" void kernel_launch(void* const* d_in, const int* in_sizes, int n_in,
                              void* d_out, int out_size) {
    (void)in_sizes; (void)n_in; (void)out_size;
    const float* rgb  = (const float*)d_in[0];
    const float* lsf  = (const float*)d_in[1];
    const float* lar  = (const float*)d_in[2];
    const float* idle = (const float*)d_in[3];
    const void*  ms   = d_in[4];
    const void*  ma   = d_in[5];

    count_kernel<<<NBLK, 256>>>(ms, ma);
    output_kernel<<<NBLK, 256>>>(ms, ma, rgb, lsf, lar, idle, (float*)d_out);
}